// round 9
// baseline (speedup 1.0000x reference)
#include <cuda_runtime.h>
#include <math.h>
#include <stdint.h>

#define L_SEQ 2048
#define B_SZ  16
#define H_DIM 512
#define NS    32
#define BH    (B_SZ*H_DIM)
#define LBH   (L_SEQ*B_SZ*H_DIM)

__device__ float g_un[LBH];            // LN output, (L,B,H)
__device__ float g_yt[LBH];            // gelu output, (B,L,H), tf32-rounded
__device__ float g_wt[2*H_DIM*H_DIM];  // W, tf32-rounded
__device__ float g_rr[H_DIM*NS], g_ri[H_DIM*NS], g_cr[H_DIM*NS], g_ci[H_DIM*NS];

__device__ __forceinline__ uint32_t smem_u32(const void* p) {
    uint32_t a;
    asm("{ .reg .u64 t; cvta.to.shared.u64 t, %1; cvt.u32.u64 %0, t; }" : "=r"(a) : "l"(p));
    return a;
}
__device__ __forceinline__ float to_tf32(float x) {
    uint32_t u;
    asm("cvt.rna.tf32.f32 %0, %1;" : "=r"(u) : "f"(x));
    return __uint_as_float(u);
}

// ---------------- K0: SSM constants ----------------
__global__ void const_kernel(const float* __restrict__ log_dt, const float* __restrict__ C,
                             const float* __restrict__ log_A_real, const float* __restrict__ A_imag) {
    int idx = blockIdx.x*blockDim.x + threadIdx.x;
    if (idx >= H_DIM*NS) return;
    int h = idx >> 5;
    float dt  = expf(log_dt[h]);
    float Are = -expf(log_A_real[idx]);
    float Aim = A_imag[idx];
    float er  = expf(Are*dt);
    float rr  = er*cosf(Aim*dt), ri = er*sinf(Aim*dt);
    float nre = rr - 1.f, nim = ri;
    float den = Are*Are + Aim*Aim;
    float qre = (nre*Are + nim*Aim)/den;
    float qim = (nim*Are - nre*Aim)/den;
    float Cre = C[2*idx], Cim = C[2*idx+1];
    g_rr[idx] = rr;  g_ri[idx] = ri;
    g_cr[idx] = 2.f*(Cre*qre - Cim*qim);
    g_ci[idx] = -2.f*(Cre*qim + Cim*qre);
}

// W -> tf32-rounded copy
__global__ void wcvt_kernel(const float* __restrict__ Wm) {
    int i = blockIdx.x*blockDim.x + threadIdx.x;
    g_wt[i] = to_tf32(Wm[i]);
}

// ---------------- K1: LayerNorm over H, warp per (l,b), float4 -------------
__global__ void ln_kernel(const float* __restrict__ u, const float* __restrict__ lnw,
                          const float* __restrict__ lnb) {
    int warp = (blockIdx.x*blockDim.x + threadIdx.x) >> 5;
    int lane = threadIdx.x & 31;
    const float4* row = (const float4*)(u + (size_t)warp*H_DIM);
    float4 v[4];
    float s = 0.f, sq = 0.f;
    #pragma unroll
    for (int i = 0; i < 4; i++) {
        float4 x = row[lane + i*32];
        v[i] = x;
        s  += x.x + x.y + x.z + x.w;
        sq += x.x*x.x + x.y*x.y + x.z*x.z + x.w*x.w;
    }
    #pragma unroll
    for (int o = 16; o >= 1; o >>= 1) {
        s  += __shfl_xor_sync(0xffffffffu, s,  o);
        sq += __shfl_xor_sync(0xffffffffu, sq, o);
    }
    float mu = s*(1.f/H_DIM);
    float rstd = rsqrtf(sq*(1.f/H_DIM) - mu*mu + 1e-5f);
    float4* orow = (float4*)(g_un + (size_t)warp*H_DIM);
    const float4* w4 = (const float4*)lnw;
    const float4* b4 = (const float4*)lnb;
    #pragma unroll
    for (int i = 0; i < 4; i++) {
        int c = lane + i*32;
        float4 wv = w4[c], bv = b4[c], o;
        o.x = (v[i].x - mu)*rstd*wv.x + bv.x;
        o.y = (v[i].y - mu)*rstd*wv.y + bv.y;
        o.z = (v[i].z - mu)*rstd*wv.z + bv.z;
        o.w = (v[i].w - mu)*rstd*wv.w + bv.w;
        orow[c] = o;
    }
}

// ---------------- K2: scan + Dskip + GELU, fused transpose to (B,L,H) -------
__global__ void __launch_bounds__(512) scan_kernel(const float* __restrict__ D) {
    __shared__ float us2[16][34];
    __shared__ float ys[32][17];
    int tid = threadIdx.x, w = tid >> 5, lane = tid & 31;
    int h0 = blockIdx.x*16, b = blockIdx.y;
    int h = h0 + w, hi = h*NS + lane;
    float rr = g_rr[hi], ri = g_ri[hi], cr = g_cr[hi], ci = g_ci[hi];
    float rr2 = rr*rr - ri*ri, ri2 = 2.f*rr*ri;
    float cr1 = cr*rr + ci*ri, ci1 = ci*rr - cr*ri;
    float Dh = D[h];
    float sre = 0.f, sim = 0.f;
    int hloc = tid & 15, tt = tid >> 4;
    const float* usrc = g_un + (size_t)b*H_DIM + h0;

    for (int l0 = 0; l0 < L_SEQ; l0 += 32) {
        us2[hloc][tt] = usrc[(size_t)(l0 + tt)*BH + hloc];
        __syncthreads();
        float v[32];
        #pragma unroll
        for (int m = 0; m < 16; m++) {
            float2 uu = *(const float2*)&us2[w][2*m];
            v[2*m] = fmaf(cr1, sre, fmaf(ci1, sim, cr*uu.x));
            float nre = fmaf(rr2, sre, fmaf(-ri2, sim, fmaf(rr, uu.x, uu.y)));
            float nim = fmaf(rr2, sim, fmaf(ri2, sre, ri*uu.x));
            sre = nre; sim = nim;
            v[2*m+1] = fmaf(cr, sre, ci*sim);
        }
        float t16[16], t8[8], t4[4], t2[2], y;
        { bool hb = lane & 16;
          #pragma unroll
          for (int j = 0; j < 16; j++) {
              float r = __shfl_xor_sync(0xffffffffu, hb ? v[j] : v[j+16], 16);
              t16[j] = (hb ? v[j+16] : v[j]) + r; } }
        { bool hb = lane & 8;
          #pragma unroll
          for (int j = 0; j < 8; j++) {
              float r = __shfl_xor_sync(0xffffffffu, hb ? t16[j] : t16[j+8], 8);
              t8[j] = (hb ? t16[j+8] : t16[j]) + r; } }
        { bool hb = lane & 4;
          #pragma unroll
          for (int j = 0; j < 4; j++) {
              float r = __shfl_xor_sync(0xffffffffu, hb ? t8[j] : t8[j+4], 4);
              t4[j] = (hb ? t8[j+4] : t8[j]) + r; } }
        { bool hb = lane & 2;
          #pragma unroll
          for (int j = 0; j < 2; j++) {
              float r = __shfl_xor_sync(0xffffffffu, hb ? t4[j] : t4[j+2], 2);
              t2[j] = (hb ? t4[j+2] : t4[j]) + r; } }
        { bool hb = lane & 1;
          float r = __shfl_xor_sync(0xffffffffu, hb ? t2[0] : t2[1], 1);
          y = (hb ? t2[1] : t2[0]) + r; }
        float uch = us2[w][lane];
        float yd = y + Dh*uch;
        float ge = 0.5f*yd*(1.f + erff(yd*0.70710678118f));
        ys[lane][w] = to_tf32(ge);
        __syncthreads();
        g_yt[((size_t)b*L_SEQ + l0 + tt)*H_DIM + h0 + hloc] = ys[tt][hloc];
    }
}

// ---------------- K3: mma.sync tf32 GEMM + GLU + residual -------------------
// CTA: 128 l x 256 o-cols (even col -> a-row h0+c/2, odd -> g-row 512+h0+c/2),
// 5-stage cp.async pipeline, k=16/stage. 8 warps, warp tile 64x64.
// Dynamic smem: A stages [5][128][20] then B stages [5][256][20].
#define NKT    32
#define NSTG   5
#define A_ELEM (128*20)
#define B_ELEM (256*20)
#define SMEM_FLOATS (NSTG*(A_ELEM + B_ELEM))

__global__ void __launch_bounds__(256) mma_gemm(const float* __restrict__ bconv,
                                                const float* __restrict__ u,
                                                float* __restrict__ out) {
    extern __shared__ float sm[];
    float* Abuf = sm;
    float* Bbuf = sm + NSTG*A_ELEM;
    int tid = threadIdx.x;
    int l0 = blockIdx.x*128, h0 = blockIdx.y*128, b = blockIdx.z;
    int wid = tid >> 5, lane = tid & 31;
    int wm = wid & 1, wn = wid >> 1;          // wm: M-half(64), wn: N-quarter(64)
    int g = lane >> 2, t = lane & 3;
    const float* Abase = g_yt + ((size_t)b*L_SEQ + l0)*H_DIM;

    float c[4][8][4];
    #pragma unroll
    for (int i = 0; i < 4; i++)
        #pragma unroll
        for (int j = 0; j < 8; j++)
            #pragma unroll
            for (int q = 0; q < 4; q++) c[i][j][q] = 0.f;

    auto load_stage = [&](int kt, int s) {
        int k0 = kt*16;
        float* As = Abuf + s*A_ELEM;
        float* Bs = Bbuf + s*B_ELEM;
        {   // A: 128 rows x 16 k = 512 x 16B
            #pragma unroll
            for (int p = 0; p < 2; p++) {
                int idx = tid + p*256;
                int r = idx >> 2, seg = idx & 3;
                const float* src = Abase + (size_t)r*H_DIM + k0 + seg*4;
                uint32_t dst = smem_u32(As + r*20 + seg*4);
                asm volatile("cp.async.cg.shared.global [%0], [%1], 16;" :: "r"(dst), "l"(src));
            }
        }
        {   // B: 256 o-rows x 16 k = 1024 x 16B
            #pragma unroll
            for (int p = 0; p < 4; p++) {
                int idx = tid + p*256;
                int r = idx >> 2, seg = idx & 3;
                int orow = (r & 1) ? (H_DIM + h0 + (r >> 1)) : (h0 + (r >> 1));
                const float* src = g_wt + (size_t)orow*H_DIM + k0 + seg*4;
                uint32_t dst = smem_u32(Bs + r*20 + seg*4);
                asm volatile("cp.async.cg.shared.global [%0], [%1], 16;" :: "r"(dst), "l"(src));
            }
        }
    };
    auto compute = [&](int s) {
        const float* As = Abuf + s*A_ELEM;
        const float* Bs = Bbuf + s*B_ELEM;
        #pragma unroll
        for (int kk = 0; kk < 16; kk += 8) {
            uint32_t a[4][4], bb[8][2];
            #pragma unroll
            for (int mt = 0; mt < 4; mt++) {
                int m = wm*64 + mt*16 + g;
                a[mt][0] = __float_as_uint(As[m*20 + kk + t]);
                a[mt][1] = __float_as_uint(As[(m+8)*20 + kk + t]);
                a[mt][2] = __float_as_uint(As[m*20 + kk + t + 4]);
                a[mt][3] = __float_as_uint(As[(m+8)*20 + kk + t + 4]);
            }
            #pragma unroll
            for (int nt = 0; nt < 8; nt++) {
                int n = wn*64 + nt*8 + g;
                bb[nt][0] = __float_as_uint(Bs[n*20 + kk + t]);
                bb[nt][1] = __float_as_uint(Bs[n*20 + kk + t + 4]);
            }
            #pragma unroll
            for (int mt = 0; mt < 4; mt++)
                #pragma unroll
                for (int nt = 0; nt < 8; nt++)
                    asm volatile(
                        "mma.sync.aligned.m16n8k8.row.col.f32.tf32.tf32.f32 "
                        "{%0,%1,%2,%3}, {%4,%5,%6,%7}, {%8,%9}, {%0,%1,%2,%3};"
                        : "+f"(c[mt][nt][0]), "+f"(c[mt][nt][1]),
                          "+f"(c[mt][nt][2]), "+f"(c[mt][nt][3])
                        : "r"(a[mt][0]), "r"(a[mt][1]), "r"(a[mt][2]), "r"(a[mt][3]),
                          "r"(bb[nt][0]), "r"(bb[nt][1]));
        }
    };

    // prologue: stages 0..3 in flight (4 groups)
    #pragma unroll
    for (int s = 0; s < NSTG-1; s++) {
        load_stage(s, s);
        asm volatile("cp.async.commit_group;");
    }
    int sidx = 0;                 // kt % NSTG
    int lidx = NSTG-1;            // (kt+NSTG-1) % NSTG
    for (int kt = 0; kt < NKT; kt++) {
        asm volatile("cp.async.wait_group 3;");
        __syncthreads();
        compute(sidx);
        __syncthreads();
        if (kt + NSTG-1 < NKT) load_stage(kt + NSTG-1, lidx);
        asm volatile("cp.async.commit_group;");   // may be empty group (tail)
        if (++sidx == NSTG) sidx = 0;
        if (++lidx == NSTG) lidx = 0;
    }

    // Epilogue: c0/c1 = (a,g) at (l, h); c2/c3 at (l+8, h)
    #pragma unroll
    for (int mt = 0; mt < 4; mt++) {
        #pragma unroll
        for (int nt = 0; nt < 8; nt++) {
            int h = h0 + wn*32 + nt*4 + t;
            float bA = bconv[h], bG = bconv[H_DIM + h];
            #pragma unroll
            for (int r2 = 0; r2 < 2; r2++) {
                int l = l0 + wm*64 + mt*16 + g + r2*8;
                float av = c[mt][nt][r2*2+0] + bA;
                float gv = c[mt][nt][r2*2+1] + bG;
                size_t o = (size_t)l*BH + (size_t)b*H_DIM + h;
                out[o] = u[o] + av * (1.f/(1.f + __expf(-gv)));
            }
        }
    }
}

// ---------------------------------------------------------------------------
extern "C" void kernel_launch(void* const* d_in, const int* in_sizes, int n_in,
                              void* d_out, int out_size) {
    const float* u          = (const float*)d_in[0];
    const float* log_dt     = (const float*)d_in[1];
    const float* C          = (const float*)d_in[2];
    const float* log_A_real = (const float*)d_in[3];
    const float* A_imag     = (const float*)d_in[4];
    const float* D          = (const float*)d_in[5];
    const float* Wm         = (const float*)d_in[6];
    const float* b_conv     = (const float*)d_in[7];
    const float* ln_w       = (const float*)d_in[8];
    const float* ln_b       = (const float*)d_in[9];
    float* out = (float*)d_out;

    cudaFuncSetAttribute(mma_gemm, cudaFuncAttributeMaxDynamicSharedMemorySize,
                         SMEM_FLOATS*(int)sizeof(float));

    const_kernel<<<64, 256>>>(log_dt, C, log_A_real, A_imag);
    wcvt_kernel<<<512, 1024>>>(Wm);
    ln_kernel<<<(L_SEQ*B_SZ)/8, 256>>>(u, ln_w, ln_b);
    scan_kernel<<<dim3(H_DIM/16, B_SZ), 512>>>(D);
    mma_gemm<<<dim3(L_SEQ/128, H_DIM/128, B_SZ), 256, SMEM_FLOATS*sizeof(float)>>>(b_conv, u, out);
}

// round 10
// speedup vs baseline: 1.0012x; 1.0012x over previous
#include <cuda_runtime.h>
#include <math.h>
#include <stdint.h>

#define L_SEQ 2048
#define B_SZ  16
#define H_DIM 512
#define NS    32
#define BH    (B_SZ*H_DIM)
#define LBH   (L_SEQ*B_SZ*H_DIM)

__device__ float g_un[LBH];            // LN output, (L,B,H)
__device__ float g_yt[LBH];            // gelu output, (B,L,H), tf32-rounded
__device__ float g_wt[2*H_DIM*H_DIM];  // W, tf32-rounded
__device__ float g_rr[H_DIM*NS], g_ri[H_DIM*NS], g_cr[H_DIM*NS], g_ci[H_DIM*NS];

__device__ __forceinline__ uint32_t smem_u32(const void* p) {
    uint32_t a;
    asm("{ .reg .u64 t; cvta.to.shared.u64 t, %1; cvt.u32.u64 %0, t; }" : "=r"(a) : "l"(p));
    return a;
}
__device__ __forceinline__ float to_tf32(float x) {
    uint32_t u;
    asm("cvt.rna.tf32.f32 %0, %1;" : "=r"(u) : "f"(x));
    return __uint_as_float(u);
}

// ---------------- K0: SSM constants ----------------
__global__ void const_kernel(const float* __restrict__ log_dt, const float* __restrict__ C,
                             const float* __restrict__ log_A_real, const float* __restrict__ A_imag) {
    int idx = blockIdx.x*blockDim.x + threadIdx.x;
    if (idx >= H_DIM*NS) return;
    int h = idx >> 5;
    float dt  = expf(log_dt[h]);
    float Are = -expf(log_A_real[idx]);
    float Aim = A_imag[idx];
    float er  = expf(Are*dt);
    float rr  = er*cosf(Aim*dt), ri = er*sinf(Aim*dt);
    float nre = rr - 1.f, nim = ri;
    float den = Are*Are + Aim*Aim;
    float qre = (nre*Are + nim*Aim)/den;
    float qim = (nim*Are - nre*Aim)/den;
    float Cre = C[2*idx], Cim = C[2*idx+1];
    g_rr[idx] = rr;  g_ri[idx] = ri;
    g_cr[idx] = 2.f*(Cre*qre - Cim*qim);
    g_ci[idx] = -2.f*(Cre*qim + Cim*qre);
}

// W -> tf32-rounded copy
__global__ void wcvt_kernel(const float* __restrict__ Wm) {
    int i = blockIdx.x*blockDim.x + threadIdx.x;
    g_wt[i] = to_tf32(Wm[i]);
}

// ---------------- K1: LayerNorm over H, warp per (l,b), float4 -------------
__global__ void ln_kernel(const float* __restrict__ u, const float* __restrict__ lnw,
                          const float* __restrict__ lnb) {
    int warp = (blockIdx.x*blockDim.x + threadIdx.x) >> 5;
    int lane = threadIdx.x & 31;
    const float4* row = (const float4*)(u + (size_t)warp*H_DIM);
    float4 v[4];
    float s = 0.f, sq = 0.f;
    #pragma unroll
    for (int i = 0; i < 4; i++) {
        float4 x = row[lane + i*32];
        v[i] = x;
        s  += x.x + x.y + x.z + x.w;
        sq += x.x*x.x + x.y*x.y + x.z*x.z + x.w*x.w;
    }
    #pragma unroll
    for (int o = 16; o >= 1; o >>= 1) {
        s  += __shfl_xor_sync(0xffffffffu, s,  o);
        sq += __shfl_xor_sync(0xffffffffu, sq, o);
    }
    float mu = s*(1.f/H_DIM);
    float rstd = rsqrtf(sq*(1.f/H_DIM) - mu*mu + 1e-5f);
    float4* orow = (float4*)(g_un + (size_t)warp*H_DIM);
    const float4* w4 = (const float4*)lnw;
    const float4* b4 = (const float4*)lnb;
    #pragma unroll
    for (int i = 0; i < 4; i++) {
        int c = lane + i*32;
        float4 wv = w4[c], bv = b4[c], o;
        o.x = (v[i].x - mu)*rstd*wv.x + bv.x;
        o.y = (v[i].y - mu)*rstd*wv.y + bv.y;
        o.z = (v[i].z - mu)*rstd*wv.z + bv.z;
        o.w = (v[i].w - mu)*rstd*wv.w + bv.w;
        orow[c] = o;
    }
}

// ---------------- K2: scan + Dskip + GELU, fused transpose to (B,L,H) -------
// Block 256 thr = 8 warps; each warp handles TWO h (lanes 0-15: h_a, 16-31: h_b),
// each lane owns 2 adjacent states. Reduce: 4-stage butterfly within 16-lane
// halves over 32 t-values; lane ends with y at t = 2*(lane&15) + j.
__global__ void __launch_bounds__(256) scan_kernel(const float* __restrict__ D) {
    __shared__ float us2[16][34];
    __shared__ float ys[32][17];
    int tid = threadIdx.x, w = tid >> 5, lane = tid & 31;
    int hh = lane >> 4, lsub = lane & 15;
    int h0 = blockIdx.x*16, b = blockIdx.y;
    int hl = 2*w + hh;                 // local h in [0,16)
    int h = h0 + hl;
    const float2* rrp = (const float2*)(g_rr + h*NS);
    const float2* rip = (const float2*)(g_ri + h*NS);
    const float2* crp = (const float2*)(g_cr + h*NS);
    const float2* cip = (const float2*)(g_ci + h*NS);
    float2 rr = rrp[lsub], ri = rip[lsub], cr = crp[lsub], ci = cip[lsub];
    float rr2x = rr.x*rr.x - ri.x*ri.x, ri2x = 2.f*rr.x*ri.x;
    float cr1x = cr.x*rr.x + ci.x*ri.x, ci1x = ci.x*rr.x - cr.x*ri.x;
    float rr2y = rr.y*rr.y - ri.y*ri.y, ri2y = 2.f*rr.y*ri.y;
    float cr1y = cr.y*rr.y + ci.y*ri.y, ci1y = ci.y*rr.y - cr.y*ri.y;
    float Dh = D[h];
    float sxr = 0.f, sxi = 0.f, syr = 0.f, syi = 0.f;
    int hloc = tid & 15, tt0 = tid >> 4;   // fill/store mapping
    const float* usrc = g_un + (size_t)b*H_DIM + h0;

    for (int l0 = 0; l0 < L_SEQ; l0 += 32) {
        us2[hloc][tt0]      = usrc[(size_t)(l0 + tt0)*BH + hloc];
        us2[hloc][tt0 + 16] = usrc[(size_t)(l0 + tt0 + 16)*BH + hloc];
        __syncthreads();
        float v[32];
        #pragma unroll
        for (int m = 0; m < 16; m++) {
            float2 uu = *(const float2*)&us2[hl][2*m];   // broadcast LDS.64
            // state x (n = 2*lsub)
            float v0 = fmaf(cr1x, sxr, fmaf(ci1x, sxi, cr.x*uu.x));
            float nre = fmaf(rr2x, sxr, fmaf(-ri2x, sxi, fmaf(rr.x, uu.x, uu.y)));
            float nim = fmaf(rr2x, sxi, fmaf(ri2x, sxr, ri.x*uu.x));
            sxr = nre; sxi = nim;
            float v1 = fmaf(cr.x, sxr, ci.x*sxi);
            // state y (n = 2*lsub+1), fused into v0/v1
            v0 = fmaf(cr1y, syr, fmaf(ci1y, syi, fmaf(cr.y, uu.x, v0)));
            nre = fmaf(rr2y, syr, fmaf(-ri2y, syi, fmaf(rr.y, uu.x, uu.y)));
            nim = fmaf(rr2y, syi, fmaf(ri2y, syr, ri.y*uu.x));
            syr = nre; syi = nim;
            v1 = fmaf(cr.y, syr, fmaf(ci.y, syi, v1));
            v[2*m] = v0; v[2*m+1] = v1;
        }
        // 4-stage butterfly within 16-lane halves (xor 8,4,2,1)
        float t16[16], t8[8], t4[4], t2[2];
        { bool hb = lane & 8;
          #pragma unroll
          for (int j = 0; j < 16; j++) {
              float r = __shfl_xor_sync(0xffffffffu, hb ? v[j] : v[j+16], 8);
              t16[j] = (hb ? v[j+16] : v[j]) + r; } }
        { bool hb = lane & 4;
          #pragma unroll
          for (int j = 0; j < 8; j++) {
              float r = __shfl_xor_sync(0xffffffffu, hb ? t16[j] : t16[j+8], 4);
              t8[j] = (hb ? t16[j+8] : t16[j]) + r; } }
        { bool hb = lane & 2;
          #pragma unroll
          for (int j = 0; j < 4; j++) {
              float r = __shfl_xor_sync(0xffffffffu, hb ? t8[j] : t8[j+4], 2);
              t4[j] = (hb ? t8[j+4] : t8[j]) + r; } }
        { bool hb = lane & 1;
          #pragma unroll
          for (int j = 0; j < 2; j++) {
              float r = __shfl_xor_sync(0xffffffffu, hb ? t4[j] : t4[j+2], 1);
              t2[j] = (hb ? t4[j+2] : t4[j]) + r; } }
        // outputs: t = 2*lsub + j for this lane's h
        #pragma unroll
        for (int j = 0; j < 2; j++) {
            int te = 2*lsub + j;
            float uv = us2[hl][te];
            float yd = t2[j] + Dh*uv;
            float ge = 0.5f*yd*(1.f + erff(yd*0.70710678118f));
            ys[te][hl] = to_tf32(ge);
        }
        __syncthreads();
        g_yt[((size_t)b*L_SEQ + l0 + tt0)*H_DIM + h0 + hloc]      = ys[tt0][hloc];
        g_yt[((size_t)b*L_SEQ + l0 + tt0 + 16)*H_DIM + h0 + hloc] = ys[tt0+16][hloc];
    }
}

// ---------------- K3: mma.sync tf32 GEMM + GLU + residual (R8 version) ------
// CTA: 128 l x 128 o-cols (even col -> a-row h0+c/2, odd -> g-row 512+h0+c/2),
// K=512 in 16-wide cp.async double-buffered chunks. 8 warps, warp tile 64x32.
#define NKT 32
__global__ void __launch_bounds__(256) mma_gemm(const float* __restrict__ bconv,
                                                const float* __restrict__ u,
                                                float* __restrict__ out) {
    __shared__ float As[2][128][20];
    __shared__ float Bs[2][128][20];
    int tid = threadIdx.x;
    int l0 = blockIdx.x*128, h0 = blockIdx.y*64, b = blockIdx.z;
    int wid = tid >> 5, lane = tid & 31;
    int wm = wid & 1, wn = wid >> 1;
    int g = lane >> 2, t = lane & 3;
    const float* Abase = g_yt + ((size_t)b*L_SEQ + l0)*H_DIM;

    float c[4][4][4];
    #pragma unroll
    for (int i = 0; i < 4; i++)
        #pragma unroll
        for (int j = 0; j < 4; j++)
            #pragma unroll
            for (int q = 0; q < 4; q++) c[i][j][q] = 0.f;

    auto load_stage = [&](int kt, int buf) {
        int k0 = kt*16;
        #pragma unroll
        for (int p = 0; p < 2; p++) {
            int idx = tid + p*256;
            int r = idx >> 2, seg = idx & 3;
            const float* srcA = Abase + (size_t)r*H_DIM + k0 + seg*4;
            uint32_t dstA = smem_u32(&As[buf][r][seg*4]);
            asm volatile("cp.async.cg.shared.global [%0], [%1], 16;" :: "r"(dstA), "l"(srcA));
            int orow = (r & 1) ? (H_DIM + h0 + (r >> 1)) : (h0 + (r >> 1));
            const float* srcB = g_wt + (size_t)orow*H_DIM + k0 + seg*4;
            uint32_t dstB = smem_u32(&Bs[buf][r][seg*4]);
            asm volatile("cp.async.cg.shared.global [%0], [%1], 16;" :: "r"(dstB), "l"(srcB));
        }
    };
    auto compute = [&](int buf) {
        #pragma unroll
        for (int kk = 0; kk < 16; kk += 8) {
            uint32_t a[4][4], bb[4][2];
            #pragma unroll
            for (int mt = 0; mt < 4; mt++) {
                int m = wm*64 + mt*16 + g;
                a[mt][0] = __float_as_uint(As[buf][m][kk+t]);
                a[mt][1] = __float_as_uint(As[buf][m+8][kk+t]);
                a[mt][2] = __float_as_uint(As[buf][m][kk+t+4]);
                a[mt][3] = __float_as_uint(As[buf][m+8][kk+t+4]);
            }
            #pragma unroll
            for (int nt = 0; nt < 4; nt++) {
                int n = wn*32 + nt*8 + g;
                bb[nt][0] = __float_as_uint(Bs[buf][n][kk+t]);
                bb[nt][1] = __float_as_uint(Bs[buf][n][kk+t+4]);
            }
            #pragma unroll
            for (int mt = 0; mt < 4; mt++)
                #pragma unroll
                for (int nt = 0; nt < 4; nt++)
                    asm volatile(
                        "mma.sync.aligned.m16n8k8.row.col.f32.tf32.tf32.f32 "
                        "{%0,%1,%2,%3}, {%4,%5,%6,%7}, {%8,%9}, {%0,%1,%2,%3};"
                        : "+f"(c[mt][nt][0]), "+f"(c[mt][nt][1]),
                          "+f"(c[mt][nt][2]), "+f"(c[mt][nt][3])
                        : "r"(a[mt][0]), "r"(a[mt][1]), "r"(a[mt][2]), "r"(a[mt][3]),
                          "r"(bb[nt][0]), "r"(bb[nt][1]));
        }
    };

    load_stage(0, 0);
    asm volatile("cp.async.commit_group;");
    for (int kt = 0; kt < NKT; kt++) {
        if (kt + 1 < NKT) {
            load_stage(kt + 1, (kt + 1) & 1);
            asm volatile("cp.async.commit_group;");
            asm volatile("cp.async.wait_group 1;");
        } else {
            asm volatile("cp.async.wait_group 0;");
        }
        __syncthreads();
        compute(kt & 1);
        __syncthreads();
    }

    #pragma unroll
    for (int mt = 0; mt < 4; mt++) {
        #pragma unroll
        for (int nt = 0; nt < 4; nt++) {
            int h = h0 + wn*16 + nt*4 + t;
            float bA = bconv[h], bG = bconv[H_DIM + h];
            #pragma unroll
            for (int r2 = 0; r2 < 2; r2++) {
                int l = l0 + wm*64 + mt*16 + g + r2*8;
                float av = c[mt][nt][r2*2+0] + bA;
                float gv = c[mt][nt][r2*2+1] + bG;
                size_t o = (size_t)l*BH + (size_t)b*H_DIM + h;
                out[o] = u[o] + av * (1.f/(1.f + __expf(-gv)));
            }
        }
    }
}

// ---------------------------------------------------------------------------
extern "C" void kernel_launch(void* const* d_in, const int* in_sizes, int n_in,
                              void* d_out, int out_size) {
    const float* u          = (const float*)d_in[0];
    const float* log_dt     = (const float*)d_in[1];
    const float* C          = (const float*)d_in[2];
    const float* log_A_real = (const float*)d_in[3];
    const float* A_imag     = (const float*)d_in[4];
    const float* D          = (const float*)d_in[5];
    const float* Wm         = (const float*)d_in[6];
    const float* b_conv     = (const float*)d_in[7];
    const float* ln_w       = (const float*)d_in[8];
    const float* ln_b       = (const float*)d_in[9];
    float* out = (float*)d_out;

    const_kernel<<<64, 256>>>(log_dt, C, log_A_real, A_imag);
    wcvt_kernel<<<512, 1024>>>(Wm);
    ln_kernel<<<(L_SEQ*B_SZ)/8, 256>>>(u, ln_w, ln_b);
    scan_kernel<<<dim3(H_DIM/16, B_SZ), 256>>>(D);
    mma_gemm<<<dim3(L_SEQ/128, H_DIM/64, B_SZ), 256>>>(b_conv, u, out);
}

// round 11
// speedup vs baseline: 1.0866x; 1.0853x over previous
#include <cuda_runtime.h>
#include <math.h>
#include <stdint.h>

#define L_SEQ 2048
#define B_SZ  16
#define H_DIM 512
#define NS    32
#define BH    (B_SZ*H_DIM)
#define LBH   (L_SEQ*B_SZ*H_DIM)

__device__ float g_un[LBH];            // LN output, (L,B,H)
__device__ float g_yt[LBH];            // gelu output, (B,L,H), tf32-rounded
__device__ float g_wt[2*H_DIM*H_DIM];  // W, tf32-rounded
__device__ float g_rr[H_DIM*NS], g_ri[H_DIM*NS], g_cr[H_DIM*NS], g_ci[H_DIM*NS];

__device__ __forceinline__ uint32_t smem_u32(const void* p) {
    uint32_t a;
    asm("{ .reg .u64 t; cvta.to.shared.u64 t, %1; cvt.u32.u64 %0, t; }" : "=r"(a) : "l"(p));
    return a;
}
__device__ __forceinline__ float to_tf32(float x) {
    uint32_t u;
    asm("cvt.rna.tf32.f32 %0, %1;" : "=r"(u) : "f"(x));
    return __uint_as_float(u);
}

// ---------------- K0: SSM constants ----------------
__global__ void const_kernel(const float* __restrict__ log_dt, const float* __restrict__ C,
                             const float* __restrict__ log_A_real, const float* __restrict__ A_imag) {
    int idx = blockIdx.x*blockDim.x + threadIdx.x;
    if (idx >= H_DIM*NS) return;
    int h = idx >> 5;
    float dt  = expf(log_dt[h]);
    float Are = -expf(log_A_real[idx]);
    float Aim = A_imag[idx];
    float er  = expf(Are*dt);
    float rr  = er*cosf(Aim*dt), ri = er*sinf(Aim*dt);
    float nre = rr - 1.f, nim = ri;
    float den = Are*Are + Aim*Aim;
    float qre = (nre*Are + nim*Aim)/den;
    float qim = (nim*Are - nre*Aim)/den;
    float Cre = C[2*idx], Cim = C[2*idx+1];
    g_rr[idx] = rr;  g_ri[idx] = ri;
    g_cr[idx] = 2.f*(Cre*qre - Cim*qim);
    g_ci[idx] = -2.f*(Cre*qim + Cim*qre);
}

// W -> tf32-rounded copy
__global__ void wcvt_kernel(const float* __restrict__ Wm) {
    int i = blockIdx.x*blockDim.x + threadIdx.x;
    g_wt[i] = to_tf32(Wm[i]);
}

// ---------------- K1: LayerNorm over H, warp per (l,b), float4 -------------
__global__ void ln_kernel(const float* __restrict__ u, const float* __restrict__ lnw,
                          const float* __restrict__ lnb) {
    int warp = (blockIdx.x*blockDim.x + threadIdx.x) >> 5;
    int lane = threadIdx.x & 31;
    const float4* row = (const float4*)(u + (size_t)warp*H_DIM);
    float4 v[4];
    float s = 0.f, sq = 0.f;
    #pragma unroll
    for (int i = 0; i < 4; i++) {
        float4 x = row[lane + i*32];
        v[i] = x;
        s  += x.x + x.y + x.z + x.w;
        sq += x.x*x.x + x.y*x.y + x.z*x.z + x.w*x.w;
    }
    #pragma unroll
    for (int o = 16; o >= 1; o >>= 1) {
        s  += __shfl_xor_sync(0xffffffffu, s,  o);
        sq += __shfl_xor_sync(0xffffffffu, sq, o);
    }
    float mu = s*(1.f/H_DIM);
    float rstd = rsqrtf(sq*(1.f/H_DIM) - mu*mu + 1e-5f);
    float4* orow = (float4*)(g_un + (size_t)warp*H_DIM);
    const float4* w4 = (const float4*)lnw;
    const float4* b4 = (const float4*)lnb;
    #pragma unroll
    for (int i = 0; i < 4; i++) {
        int c = lane + i*32;
        float4 wv = w4[c], bv = b4[c], o;
        o.x = (v[i].x - mu)*rstd*wv.x + bv.x;
        o.y = (v[i].y - mu)*rstd*wv.y + bv.y;
        o.z = (v[i].z - mu)*rstd*wv.z + bv.z;
        o.w = (v[i].w - mu)*rstd*wv.w + bv.w;
        orow[c] = o;
    }
}

// ---------------- K2: scan + Dskip + GELU (R8 version, measured 306us) ------
__global__ void __launch_bounds__(512) scan_kernel(const float* __restrict__ D) {
    __shared__ float us2[16][34];
    __shared__ float ys[32][17];
    int tid = threadIdx.x, w = tid >> 5, lane = tid & 31;
    int h0 = blockIdx.x*16, b = blockIdx.y;
    int h = h0 + w, hi = h*NS + lane;
    float rr = g_rr[hi], ri = g_ri[hi], cr = g_cr[hi], ci = g_ci[hi];
    float rr2 = rr*rr - ri*ri, ri2 = 2.f*rr*ri;
    float cr1 = cr*rr + ci*ri, ci1 = ci*rr - cr*ri;
    float Dh = D[h];
    float sre = 0.f, sim = 0.f;
    int hloc = tid & 15, tt = tid >> 4;
    const float* usrc = g_un + (size_t)b*H_DIM + h0;

    for (int l0 = 0; l0 < L_SEQ; l0 += 32) {
        us2[hloc][tt] = usrc[(size_t)(l0 + tt)*BH + hloc];
        __syncthreads();
        float v[32];
        #pragma unroll
        for (int m = 0; m < 16; m++) {
            float2 uu = *(const float2*)&us2[w][2*m];
            v[2*m] = fmaf(cr1, sre, fmaf(ci1, sim, cr*uu.x));
            float nre = fmaf(rr2, sre, fmaf(-ri2, sim, fmaf(rr, uu.x, uu.y)));
            float nim = fmaf(rr2, sim, fmaf(ri2, sre, ri*uu.x));
            sre = nre; sim = nim;
            v[2*m+1] = fmaf(cr, sre, ci*sim);
        }
        float t16[16], t8[8], t4[4], t2[2], y;
        { bool hb = lane & 16;
          #pragma unroll
          for (int j = 0; j < 16; j++) {
              float r = __shfl_xor_sync(0xffffffffu, hb ? v[j] : v[j+16], 16);
              t16[j] = (hb ? v[j+16] : v[j]) + r; } }
        { bool hb = lane & 8;
          #pragma unroll
          for (int j = 0; j < 8; j++) {
              float r = __shfl_xor_sync(0xffffffffu, hb ? t16[j] : t16[j+8], 8);
              t8[j] = (hb ? t16[j+8] : t16[j]) + r; } }
        { bool hb = lane & 4;
          #pragma unroll
          for (int j = 0; j < 4; j++) {
              float r = __shfl_xor_sync(0xffffffffu, hb ? t8[j] : t8[j+4], 4);
              t4[j] = (hb ? t8[j+4] : t8[j]) + r; } }
        { bool hb = lane & 2;
          #pragma unroll
          for (int j = 0; j < 2; j++) {
              float r = __shfl_xor_sync(0xffffffffu, hb ? t4[j] : t4[j+2], 2);
              t2[j] = (hb ? t4[j+2] : t4[j]) + r; } }
        { bool hb = lane & 1;
          float r = __shfl_xor_sync(0xffffffffu, hb ? t2[0] : t2[1], 1);
          y = (hb ? t2[1] : t2[0]) + r; }
        float uch = us2[w][lane];
        float yd = y + Dh*uch;
        float ge = 0.5f*yd*(1.f + erff(yd*0.70710678118f));
        ys[lane][w] = to_tf32(ge);
        __syncthreads();
        g_yt[((size_t)b*L_SEQ + l0 + tt)*H_DIM + h0 + hloc] = ys[tt][hloc];
    }
}

// ---------------- K3: mma.sync tf32 GEMM + GLU + residual -------------------
// R8 tile (128 l x 128 o-cols, warp tile 64x32) but 3-stage ring buffer with
// ONE __syncthreads per stage and 2 cp.async groups in flight.
// Dynamic smem: [3][128][20] A then [3][128][20] B = 61440 B -> 2 CTAs/SM.
#define NKT    32
#define NSTG   3
#define T_ELEM (128*20)
#define SMEM_FLOATS (NSTG*2*T_ELEM)

__global__ void __launch_bounds__(256) mma_gemm(const float* __restrict__ bconv,
                                                const float* __restrict__ u,
                                                float* __restrict__ out) {
    extern __shared__ float sm[];
    float* Abuf = sm;
    float* Bbuf = sm + NSTG*T_ELEM;
    int tid = threadIdx.x;
    int l0 = blockIdx.x*128, h0 = blockIdx.y*64, b = blockIdx.z;
    int wid = tid >> 5, lane = tid & 31;
    int wm = wid & 1, wn = wid >> 1;
    int g = lane >> 2, t = lane & 3;
    const float* Abase = g_yt + ((size_t)b*L_SEQ + l0)*H_DIM;

    float c[4][4][4];
    #pragma unroll
    for (int i = 0; i < 4; i++)
        #pragma unroll
        for (int j = 0; j < 4; j++)
            #pragma unroll
            for (int q = 0; q < 4; q++) c[i][j][q] = 0.f;

    auto load_stage = [&](int kt, int s) {
        int k0 = kt*16;
        float* As = Abuf + s*T_ELEM;
        float* Bs = Bbuf + s*T_ELEM;
        #pragma unroll
        for (int p = 0; p < 2; p++) {
            int idx = tid + p*256;
            int r = idx >> 2, seg = idx & 3;
            const float* srcA = Abase + (size_t)r*H_DIM + k0 + seg*4;
            uint32_t dstA = smem_u32(As + r*20 + seg*4);
            asm volatile("cp.async.cg.shared.global [%0], [%1], 16;" :: "r"(dstA), "l"(srcA));
            int orow = (r & 1) ? (H_DIM + h0 + (r >> 1)) : (h0 + (r >> 1));
            const float* srcB = g_wt + (size_t)orow*H_DIM + k0 + seg*4;
            uint32_t dstB = smem_u32(Bs + r*20 + seg*4);
            asm volatile("cp.async.cg.shared.global [%0], [%1], 16;" :: "r"(dstB), "l"(srcB));
        }
    };
    auto compute = [&](int s) {
        const float* As = Abuf + s*T_ELEM;
        const float* Bs = Bbuf + s*T_ELEM;
        #pragma unroll
        for (int kk = 0; kk < 16; kk += 8) {
            uint32_t a[4][4], bb[4][2];
            #pragma unroll
            for (int mt = 0; mt < 4; mt++) {
                int m = wm*64 + mt*16 + g;
                a[mt][0] = __float_as_uint(As[m*20 + kk + t]);
                a[mt][1] = __float_as_uint(As[(m+8)*20 + kk + t]);
                a[mt][2] = __float_as_uint(As[m*20 + kk + t + 4]);
                a[mt][3] = __float_as_uint(As[(m+8)*20 + kk + t + 4]);
            }
            #pragma unroll
            for (int nt = 0; nt < 4; nt++) {
                int n = wn*32 + nt*8 + g;
                bb[nt][0] = __float_as_uint(Bs[n*20 + kk + t]);
                bb[nt][1] = __float_as_uint(Bs[n*20 + kk + t + 4]);
            }
            #pragma unroll
            for (int mt = 0; mt < 4; mt++)
                #pragma unroll
                for (int nt = 0; nt < 4; nt++)
                    asm volatile(
                        "mma.sync.aligned.m16n8k8.row.col.f32.tf32.tf32.f32 "
                        "{%0,%1,%2,%3}, {%4,%5,%6,%7}, {%8,%9}, {%0,%1,%2,%3};"
                        : "+f"(c[mt][nt][0]), "+f"(c[mt][nt][1]),
                          "+f"(c[mt][nt][2]), "+f"(c[mt][nt][3])
                        : "r"(a[mt][0]), "r"(a[mt][1]), "r"(a[mt][2]), "r"(a[mt][3]),
                          "r"(bb[nt][0]), "r"(bb[nt][1]));
        }
    };

    // prologue: stages 0,1 in flight
    load_stage(0, 0);
    asm volatile("cp.async.commit_group;");
    load_stage(1, 1);
    asm volatile("cp.async.commit_group;");
    int sidx = 0, lidx = 2;
    for (int kt = 0; kt < NKT; kt++) {
        asm volatile("cp.async.wait_group 1;");   // stage kt resident
        __syncthreads();                          // also guards ring reuse
        if (kt + 2 < NKT) load_stage(kt + 2, lidx);
        asm volatile("cp.async.commit_group;");   // (possibly empty) group
        compute(sidx);
        if (++sidx == NSTG) sidx = 0;
        if (++lidx == NSTG) lidx = 0;
    }

    // Epilogue: c0/c1 = (a,g) at (l, h); c2/c3 at (l+8, h)
    #pragma unroll
    for (int mt = 0; mt < 4; mt++) {
        #pragma unroll
        for (int nt = 0; nt < 4; nt++) {
            int h = h0 + wn*16 + nt*4 + t;
            float bA = bconv[h], bG = bconv[H_DIM + h];
            #pragma unroll
            for (int r2 = 0; r2 < 2; r2++) {
                int l = l0 + wm*64 + mt*16 + g + r2*8;
                float av = c[mt][nt][r2*2+0] + bA;
                float gv = c[mt][nt][r2*2+1] + bG;
                size_t o = (size_t)l*BH + (size_t)b*H_DIM + h;
                out[o] = u[o] + av * (1.f/(1.f + __expf(-gv)));
            }
        }
    }
}

// ---------------------------------------------------------------------------
extern "C" void kernel_launch(void* const* d_in, const int* in_sizes, int n_in,
                              void* d_out, int out_size) {
    const float* u          = (const float*)d_in[0];
    const float* log_dt     = (const float*)d_in[1];
    const float* C          = (const float*)d_in[2];
    const float* log_A_real = (const float*)d_in[3];
    const float* A_imag     = (const float*)d_in[4];
    const float* D          = (const float*)d_in[5];
    const float* Wm         = (const float*)d_in[6];
    const float* b_conv     = (const float*)d_in[7];
    const float* ln_w       = (const float*)d_in[8];
    const float* ln_b       = (const float*)d_in[9];
    float* out = (float*)d_out;

    cudaFuncSetAttribute(mma_gemm, cudaFuncAttributeMaxDynamicSharedMemorySize,
                         SMEM_FLOATS*(int)sizeof(float));

    const_kernel<<<64, 256>>>(log_dt, C, log_A_real, A_imag);
    wcvt_kernel<<<512, 1024>>>(Wm);
    ln_kernel<<<(L_SEQ*B_SZ)/8, 256>>>(u, ln_w, ln_b);
    scan_kernel<<<dim3(H_DIM/16, B_SZ), 512>>>(D);
    mma_gemm<<<dim3(L_SEQ/128, H_DIM/64, B_SZ), 256, SMEM_FLOATS*sizeof(float)>>>(b_conv, u, out);
}

// round 12
// speedup vs baseline: 1.3907x; 1.2799x over previous
#include <cuda_runtime.h>
#include <cuda_fp16.h>
#include <math.h>
#include <stdint.h>

#define L_SEQ 2048
#define B_SZ  16
#define H_DIM 512
#define NS    32
#define BH    (B_SZ*H_DIM)
#define LBH   (L_SEQ*B_SZ*H_DIM)

__device__ float  g_un[LBH];              // LN output, (L,B,H)
__device__ __half g_yh[LBH];              // gelu output, (B,L,H), fp16
__device__ __half g_wh[2*H_DIM*H_DIM];    // W, fp16
__device__ float g_rr[H_DIM*NS], g_ri[H_DIM*NS], g_cr[H_DIM*NS], g_ci[H_DIM*NS];

__device__ __forceinline__ uint32_t smem_u32(const void* p) {
    uint32_t a;
    asm("{ .reg .u64 t; cvta.to.shared.u64 t, %1; cvt.u32.u64 %0, t; }" : "=r"(a) : "l"(p));
    return a;
}

// ---------------- K0: SSM constants ----------------
__global__ void const_kernel(const float* __restrict__ log_dt, const float* __restrict__ C,
                             const float* __restrict__ log_A_real, const float* __restrict__ A_imag) {
    int idx = blockIdx.x*blockDim.x + threadIdx.x;
    if (idx >= H_DIM*NS) return;
    int h = idx >> 5;
    float dt  = expf(log_dt[h]);
    float Are = -expf(log_A_real[idx]);
    float Aim = A_imag[idx];
    float er  = expf(Are*dt);
    float rr  = er*cosf(Aim*dt), ri = er*sinf(Aim*dt);
    float nre = rr - 1.f, nim = ri;
    float den = Are*Are + Aim*Aim;
    float qre = (nre*Are + nim*Aim)/den;
    float qim = (nim*Are - nre*Aim)/den;
    float Cre = C[2*idx], Cim = C[2*idx+1];
    g_rr[idx] = rr;  g_ri[idx] = ri;
    g_cr[idx] = 2.f*(Cre*qre - Cim*qim);
    g_ci[idx] = -2.f*(Cre*qim + Cim*qre);
}

// W -> fp16 copy
__global__ void wcvt_kernel(const float* __restrict__ Wm) {
    int i = blockIdx.x*blockDim.x + threadIdx.x;
    g_wh[i] = __float2half_rn(Wm[i]);
}

// ---------------- K1: LayerNorm over H, warp per (l,b), float4 -------------
__global__ void ln_kernel(const float* __restrict__ u, const float* __restrict__ lnw,
                          const float* __restrict__ lnb) {
    int warp = (blockIdx.x*blockDim.x + threadIdx.x) >> 5;
    int lane = threadIdx.x & 31;
    const float4* row = (const float4*)(u + (size_t)warp*H_DIM);
    float4 v[4];
    float s = 0.f, sq = 0.f;
    #pragma unroll
    for (int i = 0; i < 4; i++) {
        float4 x = row[lane + i*32];
        v[i] = x;
        s  += x.x + x.y + x.z + x.w;
        sq += x.x*x.x + x.y*x.y + x.z*x.z + x.w*x.w;
    }
    #pragma unroll
    for (int o = 16; o >= 1; o >>= 1) {
        s  += __shfl_xor_sync(0xffffffffu, s,  o);
        sq += __shfl_xor_sync(0xffffffffu, sq, o);
    }
    float mu = s*(1.f/H_DIM);
    float rstd = rsqrtf(sq*(1.f/H_DIM) - mu*mu + 1e-5f);
    float4* orow = (float4*)(g_un + (size_t)warp*H_DIM);
    const float4* w4 = (const float4*)lnw;
    const float4* b4 = (const float4*)lnb;
    #pragma unroll
    for (int i = 0; i < 4; i++) {
        int c = lane + i*32;
        float4 wv = w4[c], bv = b4[c], o;
        o.x = (v[i].x - mu)*rstd*wv.x + bv.x;
        o.y = (v[i].y - mu)*rstd*wv.y + bv.y;
        o.z = (v[i].z - mu)*rstd*wv.z + bv.z;
        o.w = (v[i].w - mu)*rstd*wv.w + bv.w;
        orow[c] = o;
    }
}

// ---------------- K2: scan + Dskip + GELU (R8 structure, fp16 store) --------
__global__ void __launch_bounds__(512) scan_kernel(const float* __restrict__ D) {
    __shared__ float us2[16][34];
    __shared__ float ys[32][17];
    int tid = threadIdx.x, w = tid >> 5, lane = tid & 31;
    int h0 = blockIdx.x*16, b = blockIdx.y;
    int h = h0 + w, hi = h*NS + lane;
    float rr = g_rr[hi], ri = g_ri[hi], cr = g_cr[hi], ci = g_ci[hi];
    float rr2 = rr*rr - ri*ri, ri2 = 2.f*rr*ri;
    float cr1 = cr*rr + ci*ri, ci1 = ci*rr - cr*ri;
    float Dh = D[h];
    float sre = 0.f, sim = 0.f;
    int hloc = tid & 15, tt = tid >> 4;
    const float* usrc = g_un + (size_t)b*H_DIM + h0;

    for (int l0 = 0; l0 < L_SEQ; l0 += 32) {
        us2[hloc][tt] = usrc[(size_t)(l0 + tt)*BH + hloc];
        __syncthreads();
        float v[32];
        #pragma unroll
        for (int m = 0; m < 16; m++) {
            float2 uu = *(const float2*)&us2[w][2*m];
            v[2*m] = fmaf(cr1, sre, fmaf(ci1, sim, cr*uu.x));
            float nre = fmaf(rr2, sre, fmaf(-ri2, sim, fmaf(rr, uu.x, uu.y)));
            float nim = fmaf(rr2, sim, fmaf(ri2, sre, ri*uu.x));
            sre = nre; sim = nim;
            v[2*m+1] = fmaf(cr, sre, ci*sim);
        }
        float t16[16], t8[8], t4[4], t2[2], y;
        { bool hb = lane & 16;
          #pragma unroll
          for (int j = 0; j < 16; j++) {
              float r = __shfl_xor_sync(0xffffffffu, hb ? v[j] : v[j+16], 16);
              t16[j] = (hb ? v[j+16] : v[j]) + r; } }
        { bool hb = lane & 8;
          #pragma unroll
          for (int j = 0; j < 8; j++) {
              float r = __shfl_xor_sync(0xffffffffu, hb ? t16[j] : t16[j+8], 8);
              t8[j] = (hb ? t16[j+8] : t16[j]) + r; } }
        { bool hb = lane & 4;
          #pragma unroll
          for (int j = 0; j < 4; j++) {
              float r = __shfl_xor_sync(0xffffffffu, hb ? t8[j] : t8[j+4], 4);
              t4[j] = (hb ? t8[j+4] : t8[j]) + r; } }
        { bool hb = lane & 2;
          #pragma unroll
          for (int j = 0; j < 2; j++) {
              float r = __shfl_xor_sync(0xffffffffu, hb ? t4[j] : t4[j+2], 2);
              t2[j] = (hb ? t4[j+2] : t4[j]) + r; } }
        { bool hb = lane & 1;
          float r = __shfl_xor_sync(0xffffffffu, hb ? t2[0] : t2[1], 1);
          y = (hb ? t2[1] : t2[0]) + r; }
        float uch = us2[w][lane];
        float yd = y + Dh*uch;
        float ge = 0.5f*yd*(1.f + erff(yd*0.70710678118f));
        ys[lane][w] = ge;
        __syncthreads();
        g_yh[((size_t)b*L_SEQ + l0 + tt)*H_DIM + h0 + hloc] = __float2half_rn(ys[tt][hloc]);
    }
}

// ---------------- K3: mma.sync fp16 GEMM + GLU + residual -------------------
// CTA: 128 l x 128 o-cols (even col -> a-row h0+c/2, odd -> g-row 512+h0+c/2).
// fp16 operands (same 10-bit mantissa as tf32), f32 accum.
// 3-stage ring, k=32/stage (16 stages), one __syncthreads per stage.
// smem: [3][128][40] halves for A and B = 61440 B -> 2 CTAs/SM.
#define NKT    16
#define NSTG   3
#define T_H    (128*40)       // halves per stage per operand
#define SMEM_BYTES (NSTG*2*T_H*2)

__global__ void __launch_bounds__(256, 2) mma_gemm(const float* __restrict__ bconv,
                                                   const float* __restrict__ u,
                                                   float* __restrict__ out) {
    extern __shared__ __half smh[];
    __half* Abuf = smh;
    __half* Bbuf = smh + NSTG*T_H;
    int tid = threadIdx.x;
    int l0 = blockIdx.x*128, h0 = blockIdx.y*64, b = blockIdx.z;
    int wid = tid >> 5, lane = tid & 31;
    int wm = wid & 1, wn = wid >> 1;
    int g = lane >> 2, t = lane & 3;
    const __half* Abase = g_yh + ((size_t)b*L_SEQ + l0)*H_DIM;

    float c[4][4][4];
    #pragma unroll
    for (int i = 0; i < 4; i++)
        #pragma unroll
        for (int j = 0; j < 4; j++)
            #pragma unroll
            for (int q = 0; q < 4; q++) c[i][j][q] = 0.f;

    auto load_stage = [&](int kt, int s) {
        int k0 = kt*32;
        __half* As = Abuf + s*T_H;
        __half* Bs = Bbuf + s*T_H;
        #pragma unroll
        for (int p = 0; p < 2; p++) {
            int idx = tid + p*256;              // 0..511
            int r = idx >> 2, seg = idx & 3;    // row, 16B segment
            const __half* srcA = Abase + (size_t)r*H_DIM + k0 + seg*8;
            uint32_t dstA = smem_u32(As + r*40 + seg*8);
            asm volatile("cp.async.cg.shared.global [%0], [%1], 16;" :: "r"(dstA), "l"(srcA));
            int orow = (r & 1) ? (H_DIM + h0 + (r >> 1)) : (h0 + (r >> 1));
            const __half* srcB = g_wh + (size_t)orow*H_DIM + k0 + seg*8;
            uint32_t dstB = smem_u32(Bs + r*40 + seg*8);
            asm volatile("cp.async.cg.shared.global [%0], [%1], 16;" :: "r"(dstB), "l"(srcB));
        }
    };
    auto compute = [&](int s) {
        const __half* As = Abuf + s*T_H;
        const __half* Bs = Bbuf + s*T_H;
        #pragma unroll
        for (int kk = 0; kk < 32; kk += 16) {
            uint32_t a[4][4], bb[2][4];
            #pragma unroll
            for (int mt = 0; mt < 4; mt++) {   // A 16x16 frag via ldmatrix.x4
                int row = wm*64 + mt*16 + (lane & 7) + ((lane >> 3) & 1)*8;
                int col = kk + (lane >> 4)*8;
                uint32_t ad = smem_u32(As + row*40 + col);
                asm volatile("ldmatrix.sync.aligned.m8n8.x4.shared.b16 {%0,%1,%2,%3}, [%4];"
                    : "=r"(a[mt][0]), "=r"(a[mt][1]), "=r"(a[mt][2]), "=r"(a[mt][3]) : "r"(ad));
            }
            #pragma unroll
            for (int ntp = 0; ntp < 2; ntp++) {  // B: two n-groups of 8 per x4
                int row = wn*32 + ntp*16 + (lane & 7) + ((lane >= 16) ? 8 : 0);
                int col = kk + ((lane >> 3) & 1)*8;
                uint32_t ad = smem_u32(Bs + row*40 + col);
                asm volatile("ldmatrix.sync.aligned.m8n8.x4.shared.b16 {%0,%1,%2,%3}, [%4];"
                    : "=r"(bb[ntp][0]), "=r"(bb[ntp][1]), "=r"(bb[ntp][2]), "=r"(bb[ntp][3]) : "r"(ad));
            }
            #pragma unroll
            for (int mt = 0; mt < 4; mt++)
                #pragma unroll
                for (int nt = 0; nt < 4; nt++) {
                    int ntp = nt >> 1, hh = nt & 1;
                    asm volatile(
                        "mma.sync.aligned.m16n8k16.row.col.f32.f16.f16.f32 "
                        "{%0,%1,%2,%3}, {%4,%5,%6,%7}, {%8,%9}, {%0,%1,%2,%3};"
                        : "+f"(c[mt][nt][0]), "+f"(c[mt][nt][1]),
                          "+f"(c[mt][nt][2]), "+f"(c[mt][nt][3])
                        : "r"(a[mt][0]), "r"(a[mt][1]), "r"(a[mt][2]), "r"(a[mt][3]),
                          "r"(bb[ntp][hh*2]), "r"(bb[ntp][hh*2+1]));
                }
        }
    };

    load_stage(0, 0);
    asm volatile("cp.async.commit_group;");
    load_stage(1, 1);
    asm volatile("cp.async.commit_group;");
    int sidx = 0, lidx = 2;
    for (int kt = 0; kt < NKT; kt++) {
        asm volatile("cp.async.wait_group 1;");
        __syncthreads();
        if (kt + 2 < NKT) load_stage(kt + 2, lidx);
        asm volatile("cp.async.commit_group;");
        compute(sidx);
        if (++sidx == NSTG) sidx = 0;
        if (++lidx == NSTG) lidx = 0;
    }

    // Epilogue: c0/c1 = (a,g) at (l, h); c2/c3 at (l+8, h)
    #pragma unroll
    for (int mt = 0; mt < 4; mt++) {
        #pragma unroll
        for (int nt = 0; nt < 4; nt++) {
            int h = h0 + wn*16 + nt*4 + t;
            float bA = bconv[h], bG = bconv[H_DIM + h];
            #pragma unroll
            for (int r2 = 0; r2 < 2; r2++) {
                int l = l0 + wm*64 + mt*16 + g + r2*8;
                float av = c[mt][nt][r2*2+0] + bA;
                float gv = c[mt][nt][r2*2+1] + bG;
                size_t o = (size_t)l*BH + (size_t)b*H_DIM + h;
                out[o] = u[o] + av * (1.f/(1.f + __expf(-gv)));
            }
        }
    }
}

// ---------------------------------------------------------------------------
extern "C" void kernel_launch(void* const* d_in, const int* in_sizes, int n_in,
                              void* d_out, int out_size) {
    const float* u          = (const float*)d_in[0];
    const float* log_dt     = (const float*)d_in[1];
    const float* C          = (const float*)d_in[2];
    const float* log_A_real = (const float*)d_in[3];
    const float* A_imag     = (const float*)d_in[4];
    const float* D          = (const float*)d_in[5];
    const float* Wm         = (const float*)d_in[6];
    const float* b_conv     = (const float*)d_in[7];
    const float* ln_w       = (const float*)d_in[8];
    const float* ln_b       = (const float*)d_in[9];
    float* out = (float*)d_out;

    cudaFuncSetAttribute(mma_gemm, cudaFuncAttributeMaxDynamicSharedMemorySize, SMEM_BYTES);

    const_kernel<<<64, 256>>>(log_dt, C, log_A_real, A_imag);
    wcvt_kernel<<<512, 1024>>>(Wm);
    ln_kernel<<<(L_SEQ*B_SZ)/8, 256>>>(u, ln_w, ln_b);
    scan_kernel<<<dim3(H_DIM/16, B_SZ), 512>>>(D);
    mma_gemm<<<dim3(L_SEQ/128, H_DIM/64, B_SZ), 256, SMEM_BYTES>>>(b_conv, u, out);
}

// round 13
// speedup vs baseline: 1.5501x; 1.1146x over previous
#include <cuda_runtime.h>
#include <cuda_fp16.h>
#include <math.h>
#include <stdint.h>

#define L_SEQ 2048
#define B_SZ  16
#define H_DIM 512
#define NS    32
#define BH    (B_SZ*H_DIM)
#define LBH   (L_SEQ*B_SZ*H_DIM)

__device__ float  g_un[LBH];              // LN output, (L,B,H)
__device__ __half g_yh[LBH];              // gelu output, (B,L,H), fp16
__device__ __half g_wh[2*H_DIM*H_DIM];    // W, fp16
__device__ float g_rr[H_DIM*NS], g_ri[H_DIM*NS], g_cr[H_DIM*NS], g_ci[H_DIM*NS];

__device__ __forceinline__ uint32_t smem_u32(const void* p) {
    uint32_t a;
    asm("{ .reg .u64 t; cvta.to.shared.u64 t, %1; cvt.u32.u64 %0, t; }" : "=r"(a) : "l"(p));
    return a;
}

// ---------------- K0: SSM constants ----------------
__global__ void const_kernel(const float* __restrict__ log_dt, const float* __restrict__ C,
                             const float* __restrict__ log_A_real, const float* __restrict__ A_imag) {
    int idx = blockIdx.x*blockDim.x + threadIdx.x;
    if (idx >= H_DIM*NS) return;
    int h = idx >> 5;
    float dt  = expf(log_dt[h]);
    float Are = -expf(log_A_real[idx]);
    float Aim = A_imag[idx];
    float er  = expf(Are*dt);
    float rr  = er*cosf(Aim*dt), ri = er*sinf(Aim*dt);
    float nre = rr - 1.f, nim = ri;
    float den = Are*Are + Aim*Aim;
    float qre = (nre*Are + nim*Aim)/den;
    float qim = (nim*Are - nre*Aim)/den;
    float Cre = C[2*idx], Cim = C[2*idx+1];
    g_rr[idx] = rr;  g_ri[idx] = ri;
    g_cr[idx] = 2.f*(Cre*qre - Cim*qim);
    g_ci[idx] = -2.f*(Cre*qim + Cim*qre);
}

// W -> fp16 copy
__global__ void wcvt_kernel(const float* __restrict__ Wm) {
    int i = blockIdx.x*blockDim.x + threadIdx.x;
    g_wh[i] = __float2half_rn(Wm[i]);
}

// ---------------- K1: LayerNorm over H, warp per (l,b), float4 -------------
__global__ void ln_kernel(const float* __restrict__ u, const float* __restrict__ lnw,
                          const float* __restrict__ lnb) {
    int warp = (blockIdx.x*blockDim.x + threadIdx.x) >> 5;
    int lane = threadIdx.x & 31;
    const float4* row = (const float4*)(u + (size_t)warp*H_DIM);
    float4 v[4];
    float s = 0.f, sq = 0.f;
    #pragma unroll
    for (int i = 0; i < 4; i++) {
        float4 x = row[lane + i*32];
        v[i] = x;
        s  += x.x + x.y + x.z + x.w;
        sq += x.x*x.x + x.y*x.y + x.z*x.z + x.w*x.w;
    }
    #pragma unroll
    for (int o = 16; o >= 1; o >>= 1) {
        s  += __shfl_xor_sync(0xffffffffu, s,  o);
        sq += __shfl_xor_sync(0xffffffffu, sq, o);
    }
    float mu = s*(1.f/H_DIM);
    float rstd = rsqrtf(sq*(1.f/H_DIM) - mu*mu + 1e-5f);
    float4* orow = (float4*)(g_un + (size_t)warp*H_DIM);
    const float4* w4 = (const float4*)lnw;
    const float4* b4 = (const float4*)lnb;
    #pragma unroll
    for (int i = 0; i < 4; i++) {
        int c = lane + i*32;
        float4 wv = w4[c], bv = b4[c], o;
        o.x = (v[i].x - mu)*rstd*wv.x + bv.x;
        o.y = (v[i].y - mu)*rstd*wv.y + bv.y;
        o.z = (v[i].z - mu)*rstd*wv.z + bv.z;
        o.w = (v[i].w - mu)*rstd*wv.w + bv.w;
        orow[c] = o;
    }
}

// ---------------- K2: scan + Dskip + GELU, smem transpose-reduce ------------
// Block 256 thr = 8 warps = 8 h of one b. lane = state n. 32-step chunks.
// v[t] stored straight to per-warp smem vs[t][lane] (stride 36 words:
// scalar writes consecutive; float4 row reads conflict-free per quarter-warp).
// Lane t then reads row t (8x LDS.128) and tree-adds -> y[t]. No shfl reduce,
// no v[32]/t16[] register arrays.
#define VS_STRIDE 36
__global__ void __launch_bounds__(256) scan_kernel(const float* __restrict__ D) {
    __shared__ float us2[8][34];
    __shared__ float ys[32][9];
    __shared__ float vs[8][32*VS_STRIDE];
    int tid = threadIdx.x, w = tid >> 5, lane = tid & 31;
    int h0 = blockIdx.x*8, b = blockIdx.y;
    int h = h0 + w, hi = h*NS + lane;
    float rr = g_rr[hi], ri = g_ri[hi], cr = g_cr[hi], ci = g_ci[hi];
    float rr2 = rr*rr - ri*ri, ri2 = 2.f*rr*ri;
    float cr1 = cr*rr + ci*ri, ci1 = ci*rr - cr*ri;
    float Dh = D[h];
    float sre = 0.f, sim = 0.f;
    int hloc = tid & 7, tt = tid >> 3;          // fill/store mapping: 8h x 32t
    const float* usrc = g_un + (size_t)b*H_DIM + h0;
    float* vw = vs[w];

    for (int l0 = 0; l0 < L_SEQ; l0 += 32) {
        us2[hloc][tt] = usrc[(size_t)(l0 + tt)*BH + hloc];
        __syncthreads();
        #pragma unroll
        for (int m = 0; m < 16; m++) {
            float2 uu = *(const float2*)&us2[w][2*m];          // broadcast LDS.64
            float v0 = fmaf(cr1, sre, fmaf(ci1, sim, cr*uu.x));
            float nre = fmaf(rr2, sre, fmaf(-ri2, sim, fmaf(rr, uu.x, uu.y)));
            float nim = fmaf(rr2, sim, fmaf(ri2, sre, ri*uu.x));
            sre = nre; sim = nim;
            float v1 = fmaf(cr, sre, ci*sim);
            vw[(2*m)*VS_STRIDE + lane]   = v0;
            vw[(2*m+1)*VS_STRIDE + lane] = v1;
        }
        __syncwarp();
        // lane t: sum row t over the 32 states
        const float4* vr = (const float4*)(vw + lane*VS_STRIDE);
        float4 aA = vr[0], aB = vr[1];
        #pragma unroll
        for (int k = 2; k < 8; k += 2) {
            float4 p = vr[k], q = vr[k+1];
            aA.x += p.x; aA.y += p.y; aA.z += p.z; aA.w += p.w;
            aB.x += q.x; aB.y += q.y; aB.z += q.z; aB.w += q.w;
        }
        float y = ((aA.x + aB.x) + (aA.y + aB.y)) + ((aA.z + aB.z) + (aA.w + aB.w));
        float uch = us2[w][lane];
        float yd = y + Dh*uch;
        float ge = 0.5f*yd*(1.f + erff(yd*0.70710678118f));
        ys[lane][w] = ge;
        __syncthreads();
        g_yh[((size_t)b*L_SEQ + l0 + tt)*H_DIM + h0 + hloc] = __float2half_rn(ys[tt][hloc]);
    }
}

// ---------------- K3: mma.sync fp16 GEMM + GLU + residual (R12, 155us) ------
#define NKT    16
#define NSTG   3
#define T_H    (128*40)
#define SMEM_BYTES (NSTG*2*T_H*2)

__global__ void __launch_bounds__(256, 2) mma_gemm(const float* __restrict__ bconv,
                                                   const float* __restrict__ u,
                                                   float* __restrict__ out) {
    extern __shared__ __half smh[];
    __half* Abuf = smh;
    __half* Bbuf = smh + NSTG*T_H;
    int tid = threadIdx.x;
    int l0 = blockIdx.x*128, h0 = blockIdx.y*64, b = blockIdx.z;
    int wid = tid >> 5, lane = tid & 31;
    int wm = wid & 1, wn = wid >> 1;
    int g = lane >> 2, t = lane & 3;
    const __half* Abase = g_yh + ((size_t)b*L_SEQ + l0)*H_DIM;

    float c[4][4][4];
    #pragma unroll
    for (int i = 0; i < 4; i++)
        #pragma unroll
        for (int j = 0; j < 4; j++)
            #pragma unroll
            for (int q = 0; q < 4; q++) c[i][j][q] = 0.f;

    auto load_stage = [&](int kt, int s) {
        int k0 = kt*32;
        __half* As = Abuf + s*T_H;
        __half* Bs = Bbuf + s*T_H;
        #pragma unroll
        for (int p = 0; p < 2; p++) {
            int idx = tid + p*256;
            int r = idx >> 2, seg = idx & 3;
            const __half* srcA = Abase + (size_t)r*H_DIM + k0 + seg*8;
            uint32_t dstA = smem_u32(As + r*40 + seg*8);
            asm volatile("cp.async.cg.shared.global [%0], [%1], 16;" :: "r"(dstA), "l"(srcA));
            int orow = (r & 1) ? (H_DIM + h0 + (r >> 1)) : (h0 + (r >> 1));
            const __half* srcB = g_wh + (size_t)orow*H_DIM + k0 + seg*8;
            uint32_t dstB = smem_u32(Bs + r*40 + seg*8);
            asm volatile("cp.async.cg.shared.global [%0], [%1], 16;" :: "r"(dstB), "l"(srcB));
        }
    };
    auto compute = [&](int s) {
        const __half* As = Abuf + s*T_H;
        const __half* Bs = Bbuf + s*T_H;
        #pragma unroll
        for (int kk = 0; kk < 32; kk += 16) {
            uint32_t a[4][4], bb[2][4];
            #pragma unroll
            for (int mt = 0; mt < 4; mt++) {
                int row = wm*64 + mt*16 + (lane & 7) + ((lane >> 3) & 1)*8;
                int col = kk + (lane >> 4)*8;
                uint32_t ad = smem_u32(As + row*40 + col);
                asm volatile("ldmatrix.sync.aligned.m8n8.x4.shared.b16 {%0,%1,%2,%3}, [%4];"
                    : "=r"(a[mt][0]), "=r"(a[mt][1]), "=r"(a[mt][2]), "=r"(a[mt][3]) : "r"(ad));
            }
            #pragma unroll
            for (int ntp = 0; ntp < 2; ntp++) {
                int row = wn*32 + ntp*16 + (lane & 7) + ((lane >= 16) ? 8 : 0);
                int col = kk + ((lane >> 3) & 1)*8;
                uint32_t ad = smem_u32(Bs + row*40 + col);
                asm volatile("ldmatrix.sync.aligned.m8n8.x4.shared.b16 {%0,%1,%2,%3}, [%4];"
                    : "=r"(bb[ntp][0]), "=r"(bb[ntp][1]), "=r"(bb[ntp][2]), "=r"(bb[ntp][3]) : "r"(ad));
            }
            #pragma unroll
            for (int mt = 0; mt < 4; mt++)
                #pragma unroll
                for (int nt = 0; nt < 4; nt++) {
                    int ntp = nt >> 1, hh = nt & 1;
                    asm volatile(
                        "mma.sync.aligned.m16n8k16.row.col.f32.f16.f16.f32 "
                        "{%0,%1,%2,%3}, {%4,%5,%6,%7}, {%8,%9}, {%0,%1,%2,%3};"
                        : "+f"(c[mt][nt][0]), "+f"(c[mt][nt][1]),
                          "+f"(c[mt][nt][2]), "+f"(c[mt][nt][3])
                        : "r"(a[mt][0]), "r"(a[mt][1]), "r"(a[mt][2]), "r"(a[mt][3]),
                          "r"(bb[ntp][hh*2]), "r"(bb[ntp][hh*2+1]));
                }
        }
    };

    load_stage(0, 0);
    asm volatile("cp.async.commit_group;");
    load_stage(1, 1);
    asm volatile("cp.async.commit_group;");
    int sidx = 0, lidx = 2;
    for (int kt = 0; kt < NKT; kt++) {
        asm volatile("cp.async.wait_group 1;");
        __syncthreads();
        if (kt + 2 < NKT) load_stage(kt + 2, lidx);
        asm volatile("cp.async.commit_group;");
        compute(sidx);
        if (++sidx == NSTG) sidx = 0;
        if (++lidx == NSTG) lidx = 0;
    }

    #pragma unroll
    for (int mt = 0; mt < 4; mt++) {
        #pragma unroll
        for (int nt = 0; nt < 4; nt++) {
            int h = h0 + wn*16 + nt*4 + t;
            float bA = bconv[h], bG = bconv[H_DIM + h];
            #pragma unroll
            for (int r2 = 0; r2 < 2; r2++) {
                int l = l0 + wm*64 + mt*16 + g + r2*8;
                float av = c[mt][nt][r2*2+0] + bA;
                float gv = c[mt][nt][r2*2+1] + bG;
                size_t o = (size_t)l*BH + (size_t)b*H_DIM + h;
                out[o] = u[o] + av * (1.f/(1.f + __expf(-gv)));
            }
        }
    }
}

// ---------------------------------------------------------------------------
extern "C" void kernel_launch(void* const* d_in, const int* in_sizes, int n_in,
                              void* d_out, int out_size) {
    const float* u          = (const float*)d_in[0];
    const float* log_dt     = (const float*)d_in[1];
    const float* C          = (const float*)d_in[2];
    const float* log_A_real = (const float*)d_in[3];
    const float* A_imag     = (const float*)d_in[4];
    const float* D          = (const float*)d_in[5];
    const float* Wm         = (const float*)d_in[6];
    const float* b_conv     = (const float*)d_in[7];
    const float* ln_w       = (const float*)d_in[8];
    const float* ln_b       = (const float*)d_in[9];
    float* out = (float*)d_out;

    cudaFuncSetAttribute(mma_gemm, cudaFuncAttributeMaxDynamicSharedMemorySize, SMEM_BYTES);

    const_kernel<<<64, 256>>>(log_dt, C, log_A_real, A_imag);
    wcvt_kernel<<<512, 1024>>>(Wm);
    ln_kernel<<<(L_SEQ*B_SZ)/8, 256>>>(u, ln_w, ln_b);
    scan_kernel<<<dim3(H_DIM/8, B_SZ), 256>>>(D);
    mma_gemm<<<dim3(L_SEQ/128, H_DIM/64, B_SZ), 256, SMEM_BYTES>>>(b_conv, u, out);
}